// round 14
// baseline (speedup 1.0000x reference)
#include <cuda_runtime.h>
#include <cuda_fp16.h>
#include <math.h>
#include <stdint.h>

#define NN 4096
#define DD 512
#define NH 8
#define HD 64
#define NXD (NN * DD)
#define NW (DD * DD)

// Scratch (allocation-free rule: __device__ globals)
__device__ __half g_x[3 * NXD];             // query/key/value fp16 (contiguous)
__device__ __half g_w[4 * NW];              // Wq/Wk/Wv/Wo fp16
__device__ __half g_qkv[3 * NXD];           // Q(prescaled*log2e)/K/V projections fp16
__device__ __half g_ah[NXD];                // attention out fp16 row-major
__device__ __half g_sg_h[(size_t)NN * NN];  // sgconv_mat fp16
__device__ float  g_part[2 * NXD];          // split-K fp32 partials (reused)
__device__ __half g_gc_h[NXD];              // graph-conv out fp16
__device__ int    g_cnt_sg[128];            // sgconv tile counters (zero-init)
__device__ int    g_cnt_op[128];            // out-proj tile counters (zero-init)

// ---------------------------------------------------------------------------
// helpers
// ---------------------------------------------------------------------------
__device__ __forceinline__ void mma_f16(float* c, const uint32_t* a, uint32_t b0, uint32_t b1) {
    asm volatile(
        "mma.sync.aligned.m16n8k16.row.col.f32.f16.f16.f32 "
        "{%0,%1,%2,%3}, {%4,%5,%6,%7}, {%8,%9}, {%0,%1,%2,%3};"
        : "+f"(c[0]), "+f"(c[1]), "+f"(c[2]), "+f"(c[3])
        : "r"(a[0]), "r"(a[1]), "r"(a[2]), "r"(a[3]), "r"(b0), "r"(b1));
}

__device__ __forceinline__ void ldsm_x4(uint32_t* r, const void* p) {
    uint32_t a = (uint32_t)__cvta_generic_to_shared(p);
    asm volatile("ldmatrix.sync.aligned.m8n8.x4.shared.b16 {%0,%1,%2,%3}, [%4];"
                 : "=r"(r[0]), "=r"(r[1]), "=r"(r[2]), "=r"(r[3]) : "r"(a));
}
__device__ __forceinline__ void ldsm_x4_t(uint32_t* r, const void* p) {
    uint32_t a = (uint32_t)__cvta_generic_to_shared(p);
    asm volatile("ldmatrix.sync.aligned.m8n8.x4.trans.shared.b16 {%0,%1,%2,%3}, [%4];"
                 : "=r"(r[0]), "=r"(r[1]), "=r"(r[2]), "=r"(r[3]) : "r"(a));
}

__device__ __forceinline__ void cpa16(void* dst, const void* src) {
    uint32_t d = (uint32_t)__cvta_generic_to_shared(dst);
    asm volatile("cp.async.cg.shared.global [%0], [%1], 16;" :: "r"(d), "l"(src));
}
#define CP_COMMIT() asm volatile("cp.async.commit_group;")
#define CP_WAIT(n)  asm volatile("cp.async.wait_group %0;" :: "n"(n))

__device__ __forceinline__ uint32_t h2exp2_u32(uint32_t x) {
    uint32_t r;
    asm("ex2.approx.f16x2 %0, %1;" : "=r"(r) : "r"(x));
    return r;
}

__device__ __forceinline__ void cvt8(const float* __restrict__ x, __half* __restrict__ y) {
    float4 v0 = *(const float4*)x;
    float4 v1 = *(const float4*)(x + 4);
    __half2 h[4];
    h[0] = __floats2half2_rn(v0.x, v0.y);
    h[1] = __floats2half2_rn(v0.z, v0.w);
    h[2] = __floats2half2_rn(v1.x, v1.y);
    h[3] = __floats2half2_rn(v1.z, v1.w);
    *(uint4*)y = *(uint4*)h;
}

// ---------------------------------------------------------------------------
// single convert launch for the 7 small tensors (q,k,v -> g_x; W* -> g_w).
// ---------------------------------------------------------------------------
__global__ __launch_bounds__(256)
void f2h_all(const float* __restrict__ q, const float* __restrict__ k,
             const float* __restrict__ v,
             const float* __restrict__ wq, const float* __restrict__ wk,
             const float* __restrict__ wv, const float* __restrict__ wo,
             __half* __restrict__ xh, __half* __restrict__ wh) {
    size_t e = (size_t)blockIdx.x * 2048 + threadIdx.x * 8;
    const float* src;
    __half* dst;
    if (e < (size_t)3 * NXD) {
        int r = (int)(e / NXD);
        size_t off = e - (size_t)r * NXD;
        src = (r == 0 ? q : r == 1 ? k : v) + off;
        dst = xh + e;
    } else {
        size_t ew = e - (size_t)3 * NXD;
        int r = (int)(ew / NW);
        size_t off = ew - (size_t)r * NW;
        src = (r == 0 ? wq : r == 1 ? wk : r == 2 ? wv : wo) + off;
        dst = wh + ew;
    }
    cvt8(src, dst);
}

// ---------------------------------------------------------------------------
// fp16 tensor-core GEMM, fp32 accumulate. BM=128, BN=128, BK=64, 3-stage ring,
// single barrier per stage. 128 threads = 4 warps (2m x 2n), warp tile 64x64.
//   TRANSB=true : B is [N,K] row-major;  false: B is [K,N] row-major.
//   OMODE: 0 = fp32 row-major, 1 = fp16 row-major
//   SPLITK2: gridDim.z==2 planes over K; each writes its fp32 partial, bumps a
//     per-tile counter; the SECOND arriver reads the other plane's partial,
//     adds to its register accumulators (+bias), writes the final output, and
//     resets the counter to 0 (graph-replay invariant). Deterministic order.
// ---------------------------------------------------------------------------
#define ALD 72     // A smem stride (halfs)
#define BLD_T 72   // B stride, TRANSB (rows = n)
#define BLD_N 136  // B stride, non-trans (rows = k, 128 cols)

template <bool TRANSB, bool HAS_BIAS, int OMODE, bool SPLITK2>
__global__ __launch_bounds__(128, 2)
void hgemm(const __half* __restrict__ A, int lda, long sAz,
           const __half* __restrict__ B, int ldb, long sBz,
           const float* __restrict__ bias0, const float* __restrict__ bias1,
           const float* __restrict__ bias2,
           void* __restrict__ Cv, int ldc, long sCz,
           int K, float alpha0,
           float* __restrict__ part, int* __restrict__ cnt) {
    extern __shared__ __half hsm[];
    __half* As = hsm;                                  // [3][128][ALD]
    __half* Bs = hsm + 3 * 128 * ALD;                  // [3][...]
    const int BSTAGE = TRANSB ? 128 * BLD_T : 64 * BLD_N;

    const int tid = threadIdx.x;
    const int warp = tid >> 5, lane = tid & 31;
    const int g = lane >> 2, t = lane & 3;
    const int wm = warp & 1, wn = warp >> 1;
    const int bm = blockIdx.y * 128, bn = blockIdx.x * 128;
    const int z = blockIdx.z;

    A += (long)z * sAz;
    B += (long)z * sBz;
    const float* bias = (z == 0) ? bias0 : (z == 1) ? bias1 : bias2;
    const float alpha = (z == 0) ? alpha0 : 1.0f;

    const int rA = lane & 15, cA = (lane >> 4) << 3;
    const int rB = (lane & 7) + ((lane >> 4) << 3), cB = lane & 8;

    float acc[4][8][4];
#pragma unroll
    for (int mi = 0; mi < 4; mi++)
#pragma unroll
        for (int ni = 0; ni < 8; ni++)
#pragma unroll
            for (int r = 0; r < 4; r++) acc[mi][ni][r] = 0.0f;

    auto loadStage = [&](int s, int k0) {
        __half* at = As + s * 128 * ALD;
        __half* bt = Bs + s * BSTAGE;
#pragma unroll
        for (int i = 0; i < 8; i++) {                 // A: 128x64 (1024 float4)
            int f = tid + i * 128;
            int row = f >> 3, cv = f & 7;
            cpa16(at + row * ALD + cv * 8, A + (size_t)(bm + row) * lda + k0 + cv * 8);
        }
        if (TRANSB) {
#pragma unroll
            for (int i = 0; i < 8; i++) {             // B: 128(n) x 64(k)
                int f = tid + i * 128;
                int row = f >> 3, cv = f & 7;
                cpa16(bt + row * BLD_T + cv * 8, B + (size_t)(bn + row) * ldb + k0 + cv * 8);
            }
        } else {
#pragma unroll
            for (int i = 0; i < 8; i++) {             // B: 64(k) x 128(n)
                int f = tid + i * 128;
                int row = f >> 4, cv = f & 15;
                cpa16(bt + row * BLD_N + cv * 8, B + (size_t)(k0 + row) * ldb + bn + cv * 8);
            }
        }
    };

    const int NT = K / 64;
    loadStage(0, 0);
    CP_COMMIT();
    if (NT > 1) { loadStage(1, 64); CP_COMMIT(); }

    for (int kt = 0; kt < NT; kt++) {
        if (kt + 1 < NT) CP_WAIT(1); else CP_WAIT(0);
        __syncthreads();                      // single barrier per stage
        if (kt + 2 < NT) { loadStage((kt + 2) % 3, (kt + 2) * 64); CP_COMMIT(); }

        const int s = kt % 3;
        __half* at = As + s * 128 * ALD;
        __half* bt = Bs + s * BSTAGE;

#pragma unroll
        for (int kk = 0; kk < 64; kk += 16) {
            uint32_t af[4][4];
#pragma unroll
            for (int mi = 0; mi < 4; mi++)
                ldsm_x4(af[mi], at + (wm * 64 + mi * 16 + rA) * ALD + kk + cA);
#pragma unroll
            for (int nip = 0; nip < 4; nip++) {
                uint32_t bf[4];
                if (TRANSB) {
                    ldsm_x4(bf, bt + (wn * 64 + nip * 16 + rB) * BLD_T + kk + cB);
#pragma unroll
                    for (int mi = 0; mi < 4; mi++) {
                        mma_f16(acc[mi][2 * nip], af[mi], bf[0], bf[1]);
                        mma_f16(acc[mi][2 * nip + 1], af[mi], bf[2], bf[3]);
                    }
                } else {
                    ldsm_x4_t(bf, bt + (kk + rB) * BLD_N + wn * 64 + nip * 16 + cB);
#pragma unroll
                    for (int mi = 0; mi < 4; mi++) {
                        mma_f16(acc[mi][2 * nip], af[mi], bf[0], bf[2]);
                        mma_f16(acc[mi][2 * nip + 1], af[mi], bf[1], bf[3]);
                    }
                }
            }
        }
    }

    if (!SPLITK2) {
#pragma unroll
        for (int mi = 0; mi < 4; mi++) {
#pragma unroll
            for (int ni = 0; ni < 8; ni++) {
                int row0 = bm + wm * 64 + mi * 16 + g;
                int col = bn + wn * 64 + ni * 8 + 2 * t;
                float b0 = 0.0f, b1 = 0.0f;
                if (HAS_BIAS) { b0 = bias[col]; b1 = bias[col + 1]; }
                float v00 = (acc[mi][ni][0] + b0) * alpha;
                float v01 = (acc[mi][ni][1] + b1) * alpha;
                float v10 = (acc[mi][ni][2] + b0) * alpha;
                float v11 = (acc[mi][ni][3] + b1) * alpha;
                if (OMODE == 0) {
                    float* C = (float*)Cv + (long)z * sCz;
                    *(float2*)&C[(size_t)row0 * ldc + col] = make_float2(v00, v01);
                    *(float2*)&C[(size_t)(row0 + 8) * ldc + col] = make_float2(v10, v11);
                } else {
                    __half* C = (__half*)Cv + (long)z * sCz;
                    *(__half2*)&C[(size_t)row0 * ldc + col] = __floats2half2_rn(v00, v01);
                    *(__half2*)&C[(size_t)(row0 + 8) * ldc + col] = __floats2half2_rn(v10, v11);
                }
            }
        }
    } else {
        // ---- split-K2 counter-based finisher ----
        float* P = part + (long)z * NXD;     // own partial plane (layout = C)
#pragma unroll
        for (int mi = 0; mi < 4; mi++) {
#pragma unroll
            for (int ni = 0; ni < 8; ni++) {
                int row0 = bm + wm * 64 + mi * 16 + g;
                int col = bn + wn * 64 + ni * 8 + 2 * t;
                *(float2*)&P[(size_t)row0 * ldc + col] =
                    make_float2(acc[mi][ni][0], acc[mi][ni][1]);
                *(float2*)&P[(size_t)(row0 + 8) * ldc + col] =
                    make_float2(acc[mi][ni][2], acc[mi][ni][3]);
            }
        }
        __threadfence();
        __shared__ int s_ret;
        const int tile = blockIdx.y * gridDim.x + blockIdx.x;
        if (tid == 0) s_ret = atomicAdd(&cnt[tile], 1);
        __syncthreads();
        if (s_ret == 1) {                    // second arriver finishes the tile
            __threadfence();                 // acquire other plane's stores
            const float* Q = part + (long)(1 - z) * NXD;
#pragma unroll
            for (int mi = 0; mi < 4; mi++) {
#pragma unroll
                for (int ni = 0; ni < 8; ni++) {
                    int row0 = bm + wm * 64 + mi * 16 + g;
                    int col = bn + wn * 64 + ni * 8 + 2 * t;
                    float2 q0 = *(const float2*)&Q[(size_t)row0 * ldc + col];
                    float2 q1 = *(const float2*)&Q[(size_t)(row0 + 8) * ldc + col];
                    float b0 = 0.0f, b1 = 0.0f;
                    if (HAS_BIAS) { b0 = bias0[col]; b1 = bias0[col + 1]; }
                    float v00 = acc[mi][ni][0] + q0.x + b0;
                    float v01 = acc[mi][ni][1] + q0.y + b1;
                    float v10 = acc[mi][ni][2] + q1.x + b0;
                    float v11 = acc[mi][ni][3] + q1.y + b1;
                    if (OMODE == 0) {
                        float* C = (float*)Cv;
                        *(float2*)&C[(size_t)row0 * ldc + col] = make_float2(v00, v01);
                        *(float2*)&C[(size_t)(row0 + 8) * ldc + col] = make_float2(v10, v11);
                    } else {
                        __half* C = (__half*)Cv;
                        *(__half2*)&C[(size_t)row0 * ldc + col] = __floats2half2_rn(v00, v01);
                        *(__half2*)&C[(size_t)(row0 + 8) * ldc + col] = __floats2half2_rn(v10, v11);
                    }
                }
            }
            __syncthreads();
            if (tid == 0) cnt[tile] = 0;     // reset for next launch / replay
        }
    }
}

// ---------------------------------------------------------------------------
// Fused flash attention (single barrier per KV tile) + concurrent sgconv
// convert plane. grid (32, NH+1): y<NH attention (256 CTAs), y==NH 32 convert
// CTAs filling the spare resident slots (256+32=288 <= 296, one wave).
// ---------------------------------------------------------------------------
#define BQ 128
#define BKV 64
#define LDH 72

__global__ __launch_bounds__(128, 2)
void flash_attn(const __half* __restrict__ Qh, const __half* __restrict__ Kh,
                const __half* __restrict__ V, __half* __restrict__ O,
                const float* __restrict__ cvt_src, __half* __restrict__ cvt_dst) {
    // ---- convert plane ----
    if (blockIdx.y == NH) {
        const int tid = threadIdx.x;
        const size_t share = (size_t)NN * NN / 32;     // 524288 elems per CTA
        size_t base = (size_t)blockIdx.x * share;
#pragma unroll 8
        for (int it = 0; it < (int)(share / 1024); it++) {
            size_t i = base + (size_t)it * 1024 + tid * 8;
            cvt8(cvt_src + i, cvt_dst + i);
        }
        return;
    }

    extern __shared__ __half sm[];
    __half* Qs = sm;                        // [BQ][LDH]
    __half* Ks = Qs + BQ * LDH;             // [3][BKV][LDH]
    __half* Vs = Ks + 3 * BKV * LDH;        // [3][BKV][LDH]

    const int h = blockIdx.y;
    const int q0 = blockIdx.x * BQ;
    const int tid = threadIdx.x;
    const int warp = tid >> 5, lane = tid & 31;
    const int g = lane >> 2, t = lane & 3;

    const int rA = lane & 15, cA = (lane >> 4) << 3;
    const int rB = (lane & 7) + ((lane >> 4) << 3), cB = lane & 8;

#pragma unroll
    for (int i = 0; i < 8; i++) {
        int f = tid + i * 128;
        int row = f >> 3, cv = f & 7;
        cpa16(&Qs[row * LDH + cv * 8], Qh + (size_t)(q0 + row) * DD + h * HD + cv * 8);
    }

    auto loadKV = [&](int s, int kv0) {
#pragma unroll
        for (int i = 0; i < 4; i++) {
            int f = tid + i * 128;
            int row = f >> 3, cv = f & 7;
            cpa16(&Ks[(s * BKV + row) * LDH + cv * 8],
                  Kh + (size_t)(kv0 + row) * DD + h * HD + cv * 8);
        }
#pragma unroll
        for (int i = 0; i < 4; i++) {
            int f = tid + i * 128;
            int row = f >> 3, cv = f & 7;
            cpa16(&Vs[(s * BKV + row) * LDH + cv * 8],
                  V + (size_t)(kv0 + row) * DD + h * HD + cv * 8);
        }
    };

    loadKV(0, 0);
    CP_COMMIT();
    loadKV(1, BKV);
    CP_COMMIT();

    CP_WAIT(1);
    __syncthreads();

    uint32_t qa[4][2][4];
#pragma unroll
    for (int ks = 0; ks < 4; ks++)
#pragma unroll
        for (int mi = 0; mi < 2; mi++)
            ldsm_x4(qa[ks][mi], &Qs[(warp * 32 + mi * 16 + rA) * LDH + ks * 16 + cA]);

    float o[2][8][4];
#pragma unroll
    for (int mi = 0; mi < 2; mi++)
#pragma unroll
        for (int ni = 0; ni < 8; ni++)
#pragma unroll
            for (int r = 0; r < 4; r++) o[mi][ni][r] = 0.0f;
    float l[2][2] = {{0.0f, 0.0f}, {0.0f, 0.0f}};

    const int NT = NN / BKV;
    for (int it = 0; it < NT; it++) {
        if (it > 0) {
            if (it + 1 < NT) CP_WAIT(1); else CP_WAIT(0);
            __syncthreads();                // single barrier per tile
        }
        if (it + 2 < NT) { loadKV((it + 2) % 3, (it + 2) * BKV); CP_COMMIT(); }

        const int s = it % 3;

        // ---- S' = (Q*log2e/sqrt(D)) K^T ----
        float sc[2][8][4];
#pragma unroll
        for (int mi = 0; mi < 2; mi++)
#pragma unroll
            for (int ni = 0; ni < 8; ni++)
#pragma unroll
                for (int r = 0; r < 4; r++) sc[mi][ni][r] = 0.0f;

#pragma unroll
        for (int ks = 0; ks < 4; ks++) {
#pragma unroll
            for (int nip = 0; nip < 4; nip++) {
                uint32_t b[4];
                ldsm_x4(b, &Ks[(s * BKV + nip * 16 + rB) * LDH + ks * 16 + cB]);
#pragma unroll
                for (int mi = 0; mi < 2; mi++) {
                    mma_f16(sc[mi][2 * nip], qa[ks][mi], b[0], b[1]);
                    mma_f16(sc[mi][2 * nip + 1], qa[ks][mi], b[2], b[3]);
                }
            }
        }

        // ---- P = exp2(S') in fp16x2; l summed from the same P ----
        uint32_t ph[2][8][2];
#pragma unroll
        for (int mi = 0; mi < 2; mi++) {
            float ps0 = 0.0f, ps1 = 0.0f;
#pragma unroll
            for (int ni = 0; ni < 8; ni++) {
                __half2 h0 = __floats2half2_rn(sc[mi][ni][0], sc[mi][ni][1]);
                __half2 h1 = __floats2half2_rn(sc[mi][ni][2], sc[mi][ni][3]);
                uint32_t e0 = h2exp2_u32(*(uint32_t*)&h0);
                uint32_t e1 = h2exp2_u32(*(uint32_t*)&h1);
                ph[mi][ni][0] = e0;
                ph[mi][ni][1] = e1;
                float2 f0 = __half22float2(*(__half2*)&e0);
                float2 f1 = __half22float2(*(__half2*)&e1);
                ps0 += f0.x + f0.y;
                ps1 += f1.x + f1.y;
            }
            l[mi][0] += ps0;
            l[mi][1] += ps1;
        }

        // ---- O += P V (V row-major -> trans ldsm; b reused across mi) ----
#pragma unroll
        for (int ks = 0; ks < 4; ks++) {
#pragma unroll
            for (int nip = 0; nip < 4; nip++) {
                uint32_t b[4];
                ldsm_x4_t(b, &Vs[(s * BKV + ks * 16 + rB) * LDH + nip * 16 + cB]);
#pragma unroll
                for (int mi = 0; mi < 2; mi++) {
                    uint32_t pa[4] = { ph[mi][2 * ks][0], ph[mi][2 * ks][1],
                                       ph[mi][2 * ks + 1][0], ph[mi][2 * ks + 1][1] };
                    mma_f16(o[mi][2 * nip], pa, b[0], b[2]);
                    mma_f16(o[mi][2 * nip + 1], pa, b[1], b[3]);
                }
            }
        }
    }

#pragma unroll
    for (int mi = 0; mi < 2; mi++) {
        float l0 = l[mi][0], l1 = l[mi][1];
        l0 += __shfl_xor_sync(0xffffffffu, l0, 1);
        l0 += __shfl_xor_sync(0xffffffffu, l0, 2);
        l1 += __shfl_xor_sync(0xffffffffu, l1, 1);
        l1 += __shfl_xor_sync(0xffffffffu, l1, 2);
        float inv0 = 1.0f / l0, inv1 = 1.0f / l1;
        size_t base = (size_t)(q0 + warp * 32 + mi * 16 + g) * DD + h * HD;
#pragma unroll
        for (int ni = 0; ni < 8; ni++) {
            int col = ni * 8 + 2 * t;
            *(__half2*)&O[base + col] = __floats2half2_rn(o[mi][ni][0] * inv0, o[mi][ni][1] * inv0);
            *(__half2*)&O[base + 8 * DD + col] = __floats2half2_rn(o[mi][ni][2] * inv1, o[mi][ni][3] * inv1);
        }
    }
}

// ---------------------------------------------------------------------------
// kernel_launch: query,key,value, Wq,bq, Wk,bk, Wv,bv, Wo,bo, sgconv_mat
// ---------------------------------------------------------------------------
extern "C" void kernel_launch(void* const* d_in, const int* in_sizes, int n_in,
                              void* d_out, int out_size) {
    const float* query  = (const float*)d_in[0];
    const float* key    = (const float*)d_in[1];
    const float* value  = (const float*)d_in[2];
    const float* Wq     = (const float*)d_in[3];
    const float* bq     = (const float*)d_in[4];
    const float* Wk     = (const float*)d_in[5];
    const float* bk     = (const float*)d_in[6];
    const float* Wv     = (const float*)d_in[7];
    const float* bv     = (const float*)d_in[8];
    const float* Wo     = (const float*)d_in[9];
    const float* bo     = (const float*)d_in[10];
    const float* sgconv = (const float*)d_in[11];
    float* out = (float*)d_out;

    __half *xh, *wh, *qkv, *ah, *sgh, *gch;
    float *part;
    int *cnt_sg, *cnt_op;
    cudaGetSymbolAddress((void**)&xh, g_x);
    cudaGetSymbolAddress((void**)&wh, g_w);
    cudaGetSymbolAddress((void**)&qkv, g_qkv);
    cudaGetSymbolAddress((void**)&ah, g_ah);
    cudaGetSymbolAddress((void**)&sgh, g_sg_h);
    cudaGetSymbolAddress((void**)&part, g_part);
    cudaGetSymbolAddress((void**)&gch, g_gc_h);
    cudaGetSymbolAddress((void**)&cnt_sg, g_cnt_sg);
    cudaGetSymbolAddress((void**)&cnt_op, g_cnt_op);

    const int FLASH_SMEM = (BQ * LDH + 6 * BKV * LDH) * (int)sizeof(__half);
    cudaFuncSetAttribute(flash_attn, cudaFuncAttributeMaxDynamicSharedMemorySize, FLASH_SMEM);
    const int HG_SMEM_T = (3 * 128 * ALD + 3 * 128 * BLD_T) * (int)sizeof(__half);
    const int HG_SMEM_N = (3 * 128 * ALD + 3 * 64 * BLD_N) * (int)sizeof(__half);
    cudaFuncSetAttribute(hgemm<true, true, 1, false>,  cudaFuncAttributeMaxDynamicSharedMemorySize, HG_SMEM_T);
    cudaFuncSetAttribute(hgemm<true, true, 0, true>,   cudaFuncAttributeMaxDynamicSharedMemorySize, HG_SMEM_T);
    cudaFuncSetAttribute(hgemm<false, false, 1, true>, cudaFuncAttributeMaxDynamicSharedMemorySize, HG_SMEM_N);

    // 1/sqrt(512) * log2(e): flash uses exp2
    const float qscale = 0.04419417382415922f * 1.4426950408889634f;

    // one convert launch for q,k,v + all four weights
    const int CVT_BLOCKS = (3 * NXD + 4 * NW) / 2048;   // 3584
    f2h_all<<<CVT_BLOCKS, 256>>>(query, key, value, Wq, Wk, Wv, Wo, xh, wh);

    // QKV projections, one batched launch: grid (4, 32, 3) = 384 CTAs
    dim3 gqkv(DD / 128, NN / 128, 3);
    hgemm<true, true, 1, false><<<gqkv, 128, HG_SMEM_T>>>(
        xh, DD, NXD, wh, DD, NW, bq, bk, bv, qkv, DD, NXD, DD, qscale,
        nullptr, nullptr);

    // flash attention (256 CTAs) + concurrent sgconv convert (32 CTAs)
    dim3 agrid(NN / BQ, NH + 1);
    flash_attn<<<agrid, 128, FLASH_SMEM>>>(qkv, qkv + NXD, qkv + 2 * NXD, ah,
                                           sgconv, sgh);

    // graph conv split-K=2 with fused finisher -> fp16 gch (no combine pass)
    dim3 gsg(DD / 128, NN / 128, 2);
    hgemm<false, false, 1, true><<<gsg, 128, HG_SMEM_N>>>(
        sgh, NN, 2048, ah, DD, (long)2048 * DD, nullptr, nullptr, nullptr,
        gch, DD, 0, 2048, 1.0f, part, cnt_sg);

    // output projection split-K=2 with fused finisher (+bias) -> fp32 out
    dim3 gop(DD / 128, NN / 128, 2);
    hgemm<true, true, 0, true><<<gop, 128, HG_SMEM_T>>>(
        gch, DD, 256, wh + 3 * (size_t)NW, DD, 256, bo, nullptr, nullptr,
        out, DD, 0, 256, 1.0f, part, cnt_op);
}

// round 15
// speedup vs baseline: 1.0795x; 1.0795x over previous
#include <cuda_runtime.h>
#include <cuda_fp16.h>
#include <math.h>
#include <stdint.h>

#define NN 4096
#define DD 512
#define NH 8
#define HD 64
#define NXD (NN * DD)
#define NW (DD * DD)

// Scratch (allocation-free rule: __device__ globals)
__device__ __half g_x[3 * NXD];             // query/key/value fp16 (contiguous)
__device__ __half g_w[4 * NW];              // Wq/Wk/Wv/Wo fp16
__device__ __half g_qkv[3 * NXD];           // Q(prescaled*log2e)/K/V projections fp16
__device__ __half g_ah[NXD];                // attention out fp16 row-major
__device__ __half g_sg_h[(size_t)NN * NN];  // sgconv_mat fp16
__device__ float  g_part[2 * NXD];          // sgconv split-K fp32 partials
__device__ __half g_gc_h[NXD];              // graph-conv out fp16

// ---------------------------------------------------------------------------
// helpers
// ---------------------------------------------------------------------------
__device__ __forceinline__ void mma_f16(float* c, const uint32_t* a, uint32_t b0, uint32_t b1) {
    asm volatile(
        "mma.sync.aligned.m16n8k16.row.col.f32.f16.f16.f32 "
        "{%0,%1,%2,%3}, {%4,%5,%6,%7}, {%8,%9}, {%0,%1,%2,%3};"
        : "+f"(c[0]), "+f"(c[1]), "+f"(c[2]), "+f"(c[3])
        : "r"(a[0]), "r"(a[1]), "r"(a[2]), "r"(a[3]), "r"(b0), "r"(b1));
}

__device__ __forceinline__ void ldsm_x4(uint32_t* r, const void* p) {
    uint32_t a = (uint32_t)__cvta_generic_to_shared(p);
    asm volatile("ldmatrix.sync.aligned.m8n8.x4.shared.b16 {%0,%1,%2,%3}, [%4];"
                 : "=r"(r[0]), "=r"(r[1]), "=r"(r[2]), "=r"(r[3]) : "r"(a));
}
__device__ __forceinline__ void ldsm_x4_t(uint32_t* r, const void* p) {
    uint32_t a = (uint32_t)__cvta_generic_to_shared(p);
    asm volatile("ldmatrix.sync.aligned.m8n8.x4.trans.shared.b16 {%0,%1,%2,%3}, [%4];"
                 : "=r"(r[0]), "=r"(r[1]), "=r"(r[2]), "=r"(r[3]) : "r"(a));
}

__device__ __forceinline__ void cpa16(void* dst, const void* src) {
    uint32_t d = (uint32_t)__cvta_generic_to_shared(dst);
    asm volatile("cp.async.cg.shared.global [%0], [%1], 16;" :: "r"(d), "l"(src));
}
#define CP_COMMIT() asm volatile("cp.async.commit_group;")
#define CP_WAIT(n)  asm volatile("cp.async.wait_group %0;" :: "n"(n))

__device__ __forceinline__ uint32_t h2exp2_u32(uint32_t x) {
    uint32_t r;
    asm("ex2.approx.f16x2 %0, %1;" : "=r"(r) : "r"(x));
    return r;
}

__device__ __forceinline__ void cvt8(const float* __restrict__ x, __half* __restrict__ y) {
    float4 v0 = *(const float4*)x;
    float4 v1 = *(const float4*)(x + 4);
    __half2 h[4];
    h[0] = __floats2half2_rn(v0.x, v0.y);
    h[1] = __floats2half2_rn(v0.z, v0.w);
    h[2] = __floats2half2_rn(v1.x, v1.y);
    h[3] = __floats2half2_rn(v1.z, v1.w);
    *(uint4*)y = *(uint4*)h;
}

// ---------------------------------------------------------------------------
// single convert launch for the 7 small tensors (q,k,v -> g_x; W* -> g_w).
// ---------------------------------------------------------------------------
__global__ __launch_bounds__(256)
void f2h_all(const float* __restrict__ q, const float* __restrict__ k,
             const float* __restrict__ v,
             const float* __restrict__ wq, const float* __restrict__ wk,
             const float* __restrict__ wv, const float* __restrict__ wo,
             __half* __restrict__ xh, __half* __restrict__ wh) {
    size_t e = (size_t)blockIdx.x * 2048 + threadIdx.x * 8;
    const float* src;
    __half* dst;
    if (e < (size_t)3 * NXD) {
        int r = (int)(e / NXD);
        size_t off = e - (size_t)r * NXD;
        src = (r == 0 ? q : r == 1 ? k : v) + off;
        dst = xh + e;
    } else {
        size_t ew = e - (size_t)3 * NXD;
        int r = (int)(ew / NW);
        size_t off = ew - (size_t)r * NW;
        src = (r == 0 ? wq : r == 1 ? wk : r == 2 ? wv : wo) + off;
        dst = wh + ew;
    }
    cvt8(src, dst);
}

// combine split-K partials: y = fp16(p0 + p1)
__global__ __launch_bounds__(256)
void combine2_kernel(const float* __restrict__ p, __half* __restrict__ y) {
    size_t i = ((size_t)blockIdx.x * 256 + threadIdx.x) * 4;
    float4 a = *(const float4*)&p[i];
    float4 b = *(const float4*)&p[i + NXD];
    __half2 h[2];
    h[0] = __floats2half2_rn(a.x + b.x, a.y + b.y);
    h[1] = __floats2half2_rn(a.z + b.z, a.w + b.w);
    *(uint2*)&y[i] = *(uint2*)h;
}

// ---------------------------------------------------------------------------
// fp16 tensor-core GEMM, fp32 accumulate. BM=128, BN=128, BK=64, 3-stage ring,
// single barrier per stage. 128 threads = 4 warps (2m x 2n), warp tile 64x64.
// (R13 configuration, proven best)
// ---------------------------------------------------------------------------
#define ALD 72     // A smem stride (halfs)
#define BLD_T 72   // B stride, TRANSB (rows = n)
#define BLD_N 136  // B stride, non-trans (rows = k, 128 cols)

template <bool TRANSB, bool HAS_BIAS, int OMODE>
__global__ __launch_bounds__(128, 2)
void hgemm(const __half* __restrict__ A, int lda, long sAz,
           const __half* __restrict__ B, int ldb, long sBz,
           const float* __restrict__ bias0, const float* __restrict__ bias1,
           const float* __restrict__ bias2,
           void* __restrict__ Cv, int ldc, long sCz,
           int K, float alpha0) {
    extern __shared__ __half hsm[];
    __half* As = hsm;                                  // [3][128][ALD]
    __half* Bs = hsm + 3 * 128 * ALD;                  // [3][...]
    const int BSTAGE = TRANSB ? 128 * BLD_T : 64 * BLD_N;

    const int tid = threadIdx.x;
    const int warp = tid >> 5, lane = tid & 31;
    const int g = lane >> 2, t = lane & 3;
    const int wm = warp & 1, wn = warp >> 1;
    const int bm = blockIdx.y * 128, bn = blockIdx.x * 128;
    const int z = blockIdx.z;

    A += (long)z * sAz;
    B += (long)z * sBz;
    const float* bias = (z == 0) ? bias0 : (z == 1) ? bias1 : bias2;
    const float alpha = (z == 0) ? alpha0 : 1.0f;

    const int rA = lane & 15, cA = (lane >> 4) << 3;
    const int rB = (lane & 7) + ((lane >> 4) << 3), cB = lane & 8;

    float acc[4][8][4];
#pragma unroll
    for (int mi = 0; mi < 4; mi++)
#pragma unroll
        for (int ni = 0; ni < 8; ni++)
#pragma unroll
            for (int r = 0; r < 4; r++) acc[mi][ni][r] = 0.0f;

    auto loadStage = [&](int s, int k0) {
        __half* at = As + s * 128 * ALD;
        __half* bt = Bs + s * BSTAGE;
#pragma unroll
        for (int i = 0; i < 8; i++) {                 // A: 128x64 (1024 float4)
            int f = tid + i * 128;
            int row = f >> 3, cv = f & 7;
            cpa16(at + row * ALD + cv * 8, A + (size_t)(bm + row) * lda + k0 + cv * 8);
        }
        if (TRANSB) {
#pragma unroll
            for (int i = 0; i < 8; i++) {             // B: 128(n) x 64(k)
                int f = tid + i * 128;
                int row = f >> 3, cv = f & 7;
                cpa16(bt + row * BLD_T + cv * 8, B + (size_t)(bn + row) * ldb + k0 + cv * 8);
            }
        } else {
#pragma unroll
            for (int i = 0; i < 8; i++) {             // B: 64(k) x 128(n)
                int f = tid + i * 128;
                int row = f >> 4, cv = f & 15;
                cpa16(bt + row * BLD_N + cv * 8, B + (size_t)(k0 + row) * ldb + bn + cv * 8);
            }
        }
    };

    const int NT = K / 64;
    loadStage(0, 0);
    CP_COMMIT();
    if (NT > 1) { loadStage(1, 64); CP_COMMIT(); }

    for (int kt = 0; kt < NT; kt++) {
        if (kt + 1 < NT) CP_WAIT(1); else CP_WAIT(0);
        __syncthreads();                      // single barrier per stage
        if (kt + 2 < NT) { loadStage((kt + 2) % 3, (kt + 2) * 64); CP_COMMIT(); }

        const int s = kt % 3;
        __half* at = As + s * 128 * ALD;
        __half* bt = Bs + s * BSTAGE;

#pragma unroll
        for (int kk = 0; kk < 64; kk += 16) {
            uint32_t af[4][4];
#pragma unroll
            for (int mi = 0; mi < 4; mi++)
                ldsm_x4(af[mi], at + (wm * 64 + mi * 16 + rA) * ALD + kk + cA);
#pragma unroll
            for (int nip = 0; nip < 4; nip++) {
                uint32_t bf[4];
                if (TRANSB) {
                    ldsm_x4(bf, bt + (wn * 64 + nip * 16 + rB) * BLD_T + kk + cB);
#pragma unroll
                    for (int mi = 0; mi < 4; mi++) {
                        mma_f16(acc[mi][2 * nip], af[mi], bf[0], bf[1]);
                        mma_f16(acc[mi][2 * nip + 1], af[mi], bf[2], bf[3]);
                    }
                } else {
                    ldsm_x4_t(bf, bt + (kk + rB) * BLD_N + wn * 64 + nip * 16 + cB);
#pragma unroll
                    for (int mi = 0; mi < 4; mi++) {
                        mma_f16(acc[mi][2 * nip], af[mi], bf[0], bf[2]);
                        mma_f16(acc[mi][2 * nip + 1], af[mi], bf[1], bf[3]);
                    }
                }
            }
        }
    }

#pragma unroll
    for (int mi = 0; mi < 4; mi++) {
#pragma unroll
        for (int ni = 0; ni < 8; ni++) {
            int row0 = bm + wm * 64 + mi * 16 + g;
            int col = bn + wn * 64 + ni * 8 + 2 * t;
            float b0 = 0.0f, b1 = 0.0f;
            if (HAS_BIAS) { b0 = bias[col]; b1 = bias[col + 1]; }
            float v00 = (acc[mi][ni][0] + b0) * alpha;
            float v01 = (acc[mi][ni][1] + b1) * alpha;
            float v10 = (acc[mi][ni][2] + b0) * alpha;
            float v11 = (acc[mi][ni][3] + b1) * alpha;
            if (OMODE == 0) {
                float* C = (float*)Cv + (long)z * sCz;
                *(float2*)&C[(size_t)row0 * ldc + col] = make_float2(v00, v01);
                *(float2*)&C[(size_t)(row0 + 8) * ldc + col] = make_float2(v10, v11);
            } else {
                __half* C = (__half*)Cv + (long)z * sCz;
                *(__half2*)&C[(size_t)row0 * ldc + col] = __floats2half2_rn(v00, v01);
                *(__half2*)&C[(size_t)(row0 + 8) * ldc + col] = __floats2half2_rn(v10, v11);
            }
        }
    }
}

// ---------------------------------------------------------------------------
// Fused flash attention + concurrent sgconv convert plane.
// NEW: normalizer l accumulated by tensor core (P @ ones) — deletes the
// float-side cvt/add reduction and all end shuffles; every lane ends with the
// full row sum in la[mi][0]/la[mi][2].
// ---------------------------------------------------------------------------
#define BQ 128
#define BKV 64
#define LDH 72
#define ONES_H2 0x3C003C00u   // half2(1.0, 1.0)

__global__ __launch_bounds__(128, 2)
void flash_attn(const __half* __restrict__ Qh, const __half* __restrict__ Kh,
                const __half* __restrict__ V, __half* __restrict__ O,
                const float* __restrict__ cvt_src, __half* __restrict__ cvt_dst) {
    // ---- convert plane ----
    if (blockIdx.y == NH) {
        const int tid = threadIdx.x;
        const size_t share = (size_t)NN * NN / 32;     // 524288 elems per CTA
        size_t base = (size_t)blockIdx.x * share;
#pragma unroll 8
        for (int it = 0; it < (int)(share / 1024); it++) {
            size_t i = base + (size_t)it * 1024 + tid * 8;
            cvt8(cvt_src + i, cvt_dst + i);
        }
        return;
    }

    extern __shared__ __half sm[];
    __half* Qs = sm;                        // [BQ][LDH]
    __half* Ks = Qs + BQ * LDH;             // [3][BKV][LDH]
    __half* Vs = Ks + 3 * BKV * LDH;        // [3][BKV][LDH]

    const int h = blockIdx.y;
    const int q0 = blockIdx.x * BQ;
    const int tid = threadIdx.x;
    const int warp = tid >> 5, lane = tid & 31;
    const int g = lane >> 2, t = lane & 3;

    const int rA = lane & 15, cA = (lane >> 4) << 3;
    const int rB = (lane & 7) + ((lane >> 4) << 3), cB = lane & 8;

#pragma unroll
    for (int i = 0; i < 8; i++) {
        int f = tid + i * 128;
        int row = f >> 3, cv = f & 7;
        cpa16(&Qs[row * LDH + cv * 8], Qh + (size_t)(q0 + row) * DD + h * HD + cv * 8);
    }

    auto loadKV = [&](int s, int kv0) {
#pragma unroll
        for (int i = 0; i < 4; i++) {
            int f = tid + i * 128;
            int row = f >> 3, cv = f & 7;
            cpa16(&Ks[(s * BKV + row) * LDH + cv * 8],
                  Kh + (size_t)(kv0 + row) * DD + h * HD + cv * 8);
        }
#pragma unroll
        for (int i = 0; i < 4; i++) {
            int f = tid + i * 128;
            int row = f >> 3, cv = f & 7;
            cpa16(&Vs[(s * BKV + row) * LDH + cv * 8],
                  V + (size_t)(kv0 + row) * DD + h * HD + cv * 8);
        }
    };

    loadKV(0, 0);
    CP_COMMIT();
    loadKV(1, BKV);
    CP_COMMIT();

    CP_WAIT(1);
    __syncthreads();

    uint32_t qa[4][2][4];
#pragma unroll
    for (int ks = 0; ks < 4; ks++)
#pragma unroll
        for (int mi = 0; mi < 2; mi++)
            ldsm_x4(qa[ks][mi], &Qs[(warp * 32 + mi * 16 + rA) * LDH + ks * 16 + cA]);

    float o[2][8][4];
#pragma unroll
    for (int mi = 0; mi < 2; mi++)
#pragma unroll
        for (int ni = 0; ni < 8; ni++)
#pragma unroll
            for (int r = 0; r < 4; r++) o[mi][ni][r] = 0.0f;
    float la[2][4];                          // l accumulators via P @ ones
#pragma unroll
    for (int mi = 0; mi < 2; mi++)
#pragma unroll
        for (int r = 0; r < 4; r++) la[mi][r] = 0.0f;

    const int NT = NN / BKV;
    for (int it = 0; it < NT; it++) {
        if (it > 0) {
            if (it + 1 < NT) CP_WAIT(1); else CP_WAIT(0);
            __syncthreads();                // single barrier per tile
        }
        if (it + 2 < NT) { loadKV((it + 2) % 3, (it + 2) * BKV); CP_COMMIT(); }

        const int s = it % 3;

        // ---- S' = (Q*log2e/sqrt(D)) K^T ----
        float sc[2][8][4];
#pragma unroll
        for (int mi = 0; mi < 2; mi++)
#pragma unroll
            for (int ni = 0; ni < 8; ni++)
#pragma unroll
                for (int r = 0; r < 4; r++) sc[mi][ni][r] = 0.0f;

#pragma unroll
        for (int ks = 0; ks < 4; ks++) {
#pragma unroll
            for (int nip = 0; nip < 4; nip++) {
                uint32_t b[4];
                ldsm_x4(b, &Ks[(s * BKV + nip * 16 + rB) * LDH + ks * 16 + cB]);
#pragma unroll
                for (int mi = 0; mi < 2; mi++) {
                    mma_f16(sc[mi][2 * nip], qa[ks][mi], b[0], b[1]);
                    mma_f16(sc[mi][2 * nip + 1], qa[ks][mi], b[2], b[3]);
                }
            }
        }

        // ---- P = exp2(S') in fp16x2 (no float-side sum needed) ----
        uint32_t ph[2][8][2];
#pragma unroll
        for (int mi = 0; mi < 2; mi++) {
#pragma unroll
            for (int ni = 0; ni < 8; ni++) {
                __half2 h0 = __floats2half2_rn(sc[mi][ni][0], sc[mi][ni][1]);
                __half2 h1 = __floats2half2_rn(sc[mi][ni][2], sc[mi][ni][3]);
                ph[mi][ni][0] = h2exp2_u32(*(uint32_t*)&h0);
                ph[mi][ni][1] = h2exp2_u32(*(uint32_t*)&h1);
            }
        }

        // ---- O += P V ; l += P @ ones (tensor-core row sums) ----
#pragma unroll
        for (int ks = 0; ks < 4; ks++) {
            uint32_t pa0[4] = { ph[0][2 * ks][0], ph[0][2 * ks][1],
                                ph[0][2 * ks + 1][0], ph[0][2 * ks + 1][1] };
            uint32_t pa1[4] = { ph[1][2 * ks][0], ph[1][2 * ks][1],
                                ph[1][2 * ks + 1][0], ph[1][2 * ks + 1][1] };
            mma_f16(la[0], pa0, ONES_H2, ONES_H2);
            mma_f16(la[1], pa1, ONES_H2, ONES_H2);
#pragma unroll
            for (int nip = 0; nip < 4; nip++) {
                uint32_t b[4];
                ldsm_x4_t(b, &Vs[(s * BKV + ks * 16 + rB) * LDH + nip * 16 + cB]);
                mma_f16(o[0][2 * nip], pa0, b[0], b[2]);
                mma_f16(o[0][2 * nip + 1], pa0, b[1], b[3]);
                mma_f16(o[1][2 * nip], pa1, b[0], b[2]);
                mma_f16(o[1][2 * nip + 1], pa1, b[1], b[3]);
            }
        }
    }

#pragma unroll
    for (int mi = 0; mi < 2; mi++) {
        float inv0 = 1.0f / la[mi][0];       // full row sum (all lanes agree)
        float inv1 = 1.0f / la[mi][2];
        size_t base = (size_t)(q0 + warp * 32 + mi * 16 + g) * DD + h * HD;
#pragma unroll
        for (int ni = 0; ni < 8; ni++) {
            int col = ni * 8 + 2 * t;
            *(__half2*)&O[base + col] = __floats2half2_rn(o[mi][ni][0] * inv0, o[mi][ni][1] * inv0);
            *(__half2*)&O[base + 8 * DD + col] = __floats2half2_rn(o[mi][ni][2] * inv1, o[mi][ni][3] * inv1);
        }
    }
}

// ---------------------------------------------------------------------------
// kernel_launch: query,key,value, Wq,bq, Wk,bk, Wv,bv, Wo,bo, sgconv_mat
// ---------------------------------------------------------------------------
extern "C" void kernel_launch(void* const* d_in, const int* in_sizes, int n_in,
                              void* d_out, int out_size) {
    const float* query  = (const float*)d_in[0];
    const float* key    = (const float*)d_in[1];
    const float* value  = (const float*)d_in[2];
    const float* Wq     = (const float*)d_in[3];
    const float* bq     = (const float*)d_in[4];
    const float* Wk     = (const float*)d_in[5];
    const float* bk     = (const float*)d_in[6];
    const float* Wv     = (const float*)d_in[7];
    const float* bv     = (const float*)d_in[8];
    const float* Wo     = (const float*)d_in[9];
    const float* bo     = (const float*)d_in[10];
    const float* sgconv = (const float*)d_in[11];
    float* out = (float*)d_out;

    __half *xh, *wh, *qkv, *ah, *sgh, *gch;
    float *part;
    cudaGetSymbolAddress((void**)&xh, g_x);
    cudaGetSymbolAddress((void**)&wh, g_w);
    cudaGetSymbolAddress((void**)&qkv, g_qkv);
    cudaGetSymbolAddress((void**)&ah, g_ah);
    cudaGetSymbolAddress((void**)&sgh, g_sg_h);
    cudaGetSymbolAddress((void**)&part, g_part);
    cudaGetSymbolAddress((void**)&gch, g_gc_h);

    const int FLASH_SMEM = (BQ * LDH + 6 * BKV * LDH) * (int)sizeof(__half);
    cudaFuncSetAttribute(flash_attn, cudaFuncAttributeMaxDynamicSharedMemorySize, FLASH_SMEM);
    const int HG_SMEM_T = (3 * 128 * ALD + 3 * 128 * BLD_T) * (int)sizeof(__half);
    const int HG_SMEM_N = (3 * 128 * ALD + 3 * 64 * BLD_N) * (int)sizeof(__half);
    cudaFuncSetAttribute(hgemm<true, true, 1>,   cudaFuncAttributeMaxDynamicSharedMemorySize, HG_SMEM_T);
    cudaFuncSetAttribute(hgemm<true, true, 0>,   cudaFuncAttributeMaxDynamicSharedMemorySize, HG_SMEM_T);
    cudaFuncSetAttribute(hgemm<false, false, 0>, cudaFuncAttributeMaxDynamicSharedMemorySize, HG_SMEM_N);

    // 1/sqrt(512) * log2(e): flash uses exp2
    const float qscale = 0.04419417382415922f * 1.4426950408889634f;

    // one convert launch for q,k,v + all four weights
    const int CVT_BLOCKS = (3 * NXD + 4 * NW) / 2048;   // 3584
    f2h_all<<<CVT_BLOCKS, 256>>>(query, key, value, Wq, Wk, Wv, Wo, xh, wh);

    // QKV projections, one batched launch: grid (4, 32, 3) = 384 CTAs
    dim3 gqkv(DD / 128, NN / 128, 3);
    hgemm<true, true, 1><<<gqkv, 128, HG_SMEM_T>>>(
        xh, DD, NXD, wh, DD, NW, bq, bk, bv, qkv, DD, NXD, DD, qscale);

    // flash attention (256 CTAs) + concurrent sgconv convert (32 CTAs)
    dim3 agrid(NN / BQ, NH + 1);
    flash_attn<<<agrid, 128, FLASH_SMEM>>>(qkv, qkv + NXD, qkv + 2 * NXD, ah,
                                           sgconv, sgh);

    // graph conv split-K=2: grid (4, 32, 2) = 256 CTAs, fp32 partials
    dim3 gsg(DD / 128, NN / 128, 2);
    hgemm<false, false, 0><<<gsg, 128, HG_SMEM_N>>>(
        sgh, NN, 2048, ah, DD, (long)2048 * DD, nullptr, nullptr, nullptr,
        part, DD, NXD, 2048, 1.0f);
    combine2_kernel<<<NXD / 1024, 256>>>(part, gch);

    // output projection: gc @ Wo^T + bo -> fp32
    dim3 gop(DD / 128, NN / 128, 1);
    hgemm<true, true, 0><<<gop, 128, HG_SMEM_T>>>(
        gch, DD, 0, wh + 3 * (size_t)NW, DD, 0, bo, nullptr, nullptr,
        out, DD, 0, DD, 1.0f);
}

// round 16
// speedup vs baseline: 1.0924x; 1.0119x over previous
#include <cuda_runtime.h>
#include <cuda_fp16.h>
#include <math.h>
#include <stdint.h>

#define NN 4096
#define DD 512
#define NH 8
#define HD 64
#define NXD (NN * DD)
#define NW (DD * DD)

// Scratch (allocation-free rule: __device__ globals)
__device__ __half g_x[3 * NXD];             // query/key/value fp16 (contiguous)
__device__ __half g_w[4 * NW];              // Wq/Wk/Wv/Wo fp16
__device__ __half g_qkv[3 * NXD];           // Q(prescaled*log2e)/K/V projections fp16
__device__ __half g_ah[NXD];                // attention out fp16 row-major
__device__ __half g_sg_h[(size_t)NN * NN];  // sgconv_mat fp16
__device__ __half g_parth[2 * NXD];         // sgconv split-K fp16 partials
__device__ __half g_gc_h[NXD];              // graph-conv out fp16

// ---------------------------------------------------------------------------
// helpers
// ---------------------------------------------------------------------------
__device__ __forceinline__ void mma_f16(float* c, const uint32_t* a, uint32_t b0, uint32_t b1) {
    asm volatile(
        "mma.sync.aligned.m16n8k16.row.col.f32.f16.f16.f32 "
        "{%0,%1,%2,%3}, {%4,%5,%6,%7}, {%8,%9}, {%0,%1,%2,%3};"
        : "+f"(c[0]), "+f"(c[1]), "+f"(c[2]), "+f"(c[3])
        : "r"(a[0]), "r"(a[1]), "r"(a[2]), "r"(a[3]), "r"(b0), "r"(b1));
}

__device__ __forceinline__ void ldsm_x4(uint32_t* r, const void* p) {
    uint32_t a = (uint32_t)__cvta_generic_to_shared(p);
    asm volatile("ldmatrix.sync.aligned.m8n8.x4.shared.b16 {%0,%1,%2,%3}, [%4];"
                 : "=r"(r[0]), "=r"(r[1]), "=r"(r[2]), "=r"(r[3]) : "r"(a));
}
__device__ __forceinline__ void ldsm_x4_t(uint32_t* r, const void* p) {
    uint32_t a = (uint32_t)__cvta_generic_to_shared(p);
    asm volatile("ldmatrix.sync.aligned.m8n8.x4.trans.shared.b16 {%0,%1,%2,%3}, [%4];"
                 : "=r"(r[0]), "=r"(r[1]), "=r"(r[2]), "=r"(r[3]) : "r"(a));
}

__device__ __forceinline__ void cpa16(void* dst, const void* src) {
    uint32_t d = (uint32_t)__cvta_generic_to_shared(dst);
    asm volatile("cp.async.cg.shared.global [%0], [%1], 16;" :: "r"(d), "l"(src));
}
#define CP_COMMIT() asm volatile("cp.async.commit_group;")
#define CP_WAIT(n)  asm volatile("cp.async.wait_group %0;" :: "n"(n))

__device__ __forceinline__ uint32_t h2exp2_u32(uint32_t x) {
    uint32_t r;
    asm("ex2.approx.f16x2 %0, %1;" : "=r"(r) : "r"(x));
    return r;
}

__device__ __forceinline__ void cvt8(const float* __restrict__ x, __half* __restrict__ y) {
    float4 v0 = *(const float4*)x;
    float4 v1 = *(const float4*)(x + 4);
    __half2 h[4];
    h[0] = __floats2half2_rn(v0.x, v0.y);
    h[1] = __floats2half2_rn(v0.z, v0.w);
    h[2] = __floats2half2_rn(v1.x, v1.y);
    h[3] = __floats2half2_rn(v1.z, v1.w);
    *(uint4*)y = *(uint4*)h;
}

// ---------------------------------------------------------------------------
// single convert launch for the 7 small tensors (q,k,v -> g_x; W* -> g_w).
// ---------------------------------------------------------------------------
__global__ __launch_bounds__(256)
void f2h_all(const float* __restrict__ q, const float* __restrict__ k,
             const float* __restrict__ v,
             const float* __restrict__ wq, const float* __restrict__ wk,
             const float* __restrict__ wv, const float* __restrict__ wo,
             __half* __restrict__ xh, __half* __restrict__ wh) {
    size_t e = (size_t)blockIdx.x * 2048 + threadIdx.x * 8;
    const float* src;
    __half* dst;
    if (e < (size_t)3 * NXD) {
        int r = (int)(e / NXD);
        size_t off = e - (size_t)r * NXD;
        src = (r == 0 ? q : r == 1 ? k : v) + off;
        dst = xh + e;
    } else {
        size_t ew = e - (size_t)3 * NXD;
        int r = (int)(ew / NW);
        size_t off = ew - (size_t)r * NW;
        src = (r == 0 ? wq : r == 1 ? wk : r == 2 ? wv : wo) + off;
        dst = wh + ew;
    }
    cvt8(src, dst);
}

// combine fp16 split-K partials (add in fp32): y = fp16(p0 + p1)
__global__ __launch_bounds__(256)
void combine2h_kernel(const __half* __restrict__ p, __half* __restrict__ y) {
    size_t i = ((size_t)blockIdx.x * 256 + threadIdx.x) * 8;
    uint4 a = *(const uint4*)&p[i];
    uint4 b = *(const uint4*)&p[i + NXD];
    const __half2* ah = (const __half2*)&a;
    const __half2* bh = (const __half2*)&b;
    __half2 r[4];
#pragma unroll
    for (int j = 0; j < 4; j++) {
        float2 fa = __half22float2(ah[j]);
        float2 fb = __half22float2(bh[j]);
        r[j] = __floats2half2_rn(fa.x + fb.x, fa.y + fb.y);
    }
    *(uint4*)&y[i] = *(uint4*)r;
}

// ---------------------------------------------------------------------------
// fp16 tensor-core GEMM, fp32 accumulate. BM=128, BN in {128,64}, BK=64,
// 3-stage ring, single barrier per stage. 128 threads = 4 warps (2m x 2n);
// warp tile 64 x (BN/2).
//   TRANSB=true : B is [N,K] row-major;  false: B is [K,N] row-major (BN=128).
//   OMODE: 0 = fp32 row-major, 1 = fp16 row-major
// ---------------------------------------------------------------------------
#define ALD 72     // A smem stride (halfs)
#define BLD_T 72   // B stride, TRANSB (rows = n)
#define BLD_N 136  // B stride, non-trans (rows = k, 128 cols)

template <int BN, bool TRANSB, bool HAS_BIAS, int OMODE>
__global__ __launch_bounds__(128, 2)
void hgemm(const __half* __restrict__ A, int lda, long sAz,
           const __half* __restrict__ B, int ldb, long sBz,
           const float* __restrict__ bias0, const float* __restrict__ bias1,
           const float* __restrict__ bias2,
           void* __restrict__ Cv, int ldc, long sCz,
           int K, float alpha0) {
    constexpr int WN = BN / 2;          // warp n-extent: 64 or 32
    constexpr int NI = WN / 8;          // 8 or 4
    constexpr int NIP = WN / 16;        // 4 or 2

    extern __shared__ __half hsm[];
    __half* As = hsm;                                  // [3][128][ALD]
    __half* Bs = hsm + 3 * 128 * ALD;                  // [3][...]
    const int BSTAGE = TRANSB ? BN * BLD_T : 64 * BLD_N;

    const int tid = threadIdx.x;
    const int warp = tid >> 5, lane = tid & 31;
    const int g = lane >> 2, t = lane & 3;
    const int wm = warp & 1, wn = warp >> 1;
    const int bm = blockIdx.y * 128, bn = blockIdx.x * BN;
    const int z = blockIdx.z;

    A += (long)z * sAz;
    B += (long)z * sBz;
    const float* bias = (z == 0) ? bias0 : (z == 1) ? bias1 : bias2;
    const float alpha = (z == 0) ? alpha0 : 1.0f;

    const int rA = lane & 15, cA = (lane >> 4) << 3;
    const int rB = (lane & 7) + ((lane >> 4) << 3), cB = lane & 8;

    float acc[4][NI][4];
#pragma unroll
    for (int mi = 0; mi < 4; mi++)
#pragma unroll
        for (int ni = 0; ni < NI; ni++)
#pragma unroll
            for (int r = 0; r < 4; r++) acc[mi][ni][r] = 0.0f;

    auto loadStage = [&](int s, int k0) {
        __half* at = As + s * 128 * ALD;
        __half* bt = Bs + s * BSTAGE;
#pragma unroll
        for (int i = 0; i < 8; i++) {                 // A: 128x64 (1024 float4)
            int f = tid + i * 128;
            int row = f >> 3, cv = f & 7;
            cpa16(at + row * ALD + cv * 8, A + (size_t)(bm + row) * lda + k0 + cv * 8);
        }
        if (TRANSB) {
#pragma unroll
            for (int i = 0; i < BN / 16; i++) {       // B: BN(n) x 64(k)
                int f = tid + i * 128;
                int row = f >> 3, cv = f & 7;
                cpa16(bt + row * BLD_T + cv * 8, B + (size_t)(bn + row) * ldb + k0 + cv * 8);
            }
        } else {
#pragma unroll
            for (int i = 0; i < 8; i++) {             // B: 64(k) x 128(n)
                int f = tid + i * 128;
                int row = f >> 4, cv = f & 15;
                cpa16(bt + row * BLD_N + cv * 8, B + (size_t)(k0 + row) * ldb + bn + cv * 8);
            }
        }
    };

    const int NT = K / 64;
    loadStage(0, 0);
    CP_COMMIT();
    if (NT > 1) { loadStage(1, 64); CP_COMMIT(); }

    for (int kt = 0; kt < NT; kt++) {
        if (kt + 1 < NT) CP_WAIT(1); else CP_WAIT(0);
        __syncthreads();                      // single barrier per stage
        if (kt + 2 < NT) { loadStage((kt + 2) % 3, (kt + 2) * 64); CP_COMMIT(); }

        const int s = kt % 3;
        __half* at = As + s * 128 * ALD;
        __half* bt = Bs + s * BSTAGE;

#pragma unroll
        for (int kk = 0; kk < 64; kk += 16) {
            uint32_t af[4][4];
#pragma unroll
            for (int mi = 0; mi < 4; mi++)
                ldsm_x4(af[mi], at + (wm * 64 + mi * 16 + rA) * ALD + kk + cA);
#pragma unroll
            for (int nip = 0; nip < NIP; nip++) {
                uint32_t bf[4];
                if (TRANSB) {
                    ldsm_x4(bf, bt + (wn * WN + nip * 16 + rB) * BLD_T + kk + cB);
#pragma unroll
                    for (int mi = 0; mi < 4; mi++) {
                        mma_f16(acc[mi][2 * nip], af[mi], bf[0], bf[1]);
                        mma_f16(acc[mi][2 * nip + 1], af[mi], bf[2], bf[3]);
                    }
                } else {
                    ldsm_x4_t(bf, bt + (kk + rB) * BLD_N + wn * WN + nip * 16 + cB);
#pragma unroll
                    for (int mi = 0; mi < 4; mi++) {
                        mma_f16(acc[mi][2 * nip], af[mi], bf[0], bf[2]);
                        mma_f16(acc[mi][2 * nip + 1], af[mi], bf[1], bf[3]);
                    }
                }
            }
        }
    }

#pragma unroll
    for (int mi = 0; mi < 4; mi++) {
#pragma unroll
        for (int ni = 0; ni < NI; ni++) {
            int row0 = bm + wm * 64 + mi * 16 + g;
            int col = bn + wn * WN + ni * 8 + 2 * t;
            float b0 = 0.0f, b1 = 0.0f;
            if (HAS_BIAS) { b0 = bias[col]; b1 = bias[col + 1]; }
            float v00 = (acc[mi][ni][0] + b0) * alpha;
            float v01 = (acc[mi][ni][1] + b1) * alpha;
            float v10 = (acc[mi][ni][2] + b0) * alpha;
            float v11 = (acc[mi][ni][3] + b1) * alpha;
            if (OMODE == 0) {
                float* C = (float*)Cv + (long)z * sCz;
                *(float2*)&C[(size_t)row0 * ldc + col] = make_float2(v00, v01);
                *(float2*)&C[(size_t)(row0 + 8) * ldc + col] = make_float2(v10, v11);
            } else {
                __half* C = (__half*)Cv + (long)z * sCz;
                *(__half2*)&C[(size_t)row0 * ldc + col] = __floats2half2_rn(v00, v01);
                *(__half2*)&C[(size_t)(row0 + 8) * ldc + col] = __floats2half2_rn(v10, v11);
            }
        }
    }
}

// ---------------------------------------------------------------------------
// Fused flash attention (R13 core, proven best) + concurrent sgconv convert
// plane. grid (32, NH+1): y<NH attention (256 CTAs), y==NH 32 convert CTAs.
// ---------------------------------------------------------------------------
#define BQ 128
#define BKV 64
#define LDH 72

__global__ __launch_bounds__(128, 2)
void flash_attn(const __half* __restrict__ Qh, const __half* __restrict__ Kh,
                const __half* __restrict__ V, __half* __restrict__ O,
                const float* __restrict__ cvt_src, __half* __restrict__ cvt_dst) {
    // ---- convert plane ----
    if (blockIdx.y == NH) {
        const int tid = threadIdx.x;
        const size_t share = (size_t)NN * NN / 32;     // 524288 elems per CTA
        size_t base = (size_t)blockIdx.x * share;
#pragma unroll 8
        for (int it = 0; it < (int)(share / 1024); it++) {
            size_t i = base + (size_t)it * 1024 + tid * 8;
            cvt8(cvt_src + i, cvt_dst + i);
        }
        return;
    }

    extern __shared__ __half sm[];
    __half* Qs = sm;                        // [BQ][LDH]
    __half* Ks = Qs + BQ * LDH;             // [3][BKV][LDH]
    __half* Vs = Ks + 3 * BKV * LDH;        // [3][BKV][LDH]

    const int h = blockIdx.y;
    const int q0 = blockIdx.x * BQ;
    const int tid = threadIdx.x;
    const int warp = tid >> 5, lane = tid & 31;
    const int g = lane >> 2, t = lane & 3;

    const int rA = lane & 15, cA = (lane >> 4) << 3;
    const int rB = (lane & 7) + ((lane >> 4) << 3), cB = lane & 8;

#pragma unroll
    for (int i = 0; i < 8; i++) {
        int f = tid + i * 128;
        int row = f >> 3, cv = f & 7;
        cpa16(&Qs[row * LDH + cv * 8], Qh + (size_t)(q0 + row) * DD + h * HD + cv * 8);
    }

    auto loadKV = [&](int s, int kv0) {
#pragma unroll
        for (int i = 0; i < 4; i++) {
            int f = tid + i * 128;
            int row = f >> 3, cv = f & 7;
            cpa16(&Ks[(s * BKV + row) * LDH + cv * 8],
                  Kh + (size_t)(kv0 + row) * DD + h * HD + cv * 8);
        }
#pragma unroll
        for (int i = 0; i < 4; i++) {
            int f = tid + i * 128;
            int row = f >> 3, cv = f & 7;
            cpa16(&Vs[(s * BKV + row) * LDH + cv * 8],
                  V + (size_t)(kv0 + row) * DD + h * HD + cv * 8);
        }
    };

    loadKV(0, 0);
    CP_COMMIT();
    loadKV(1, BKV);
    CP_COMMIT();

    CP_WAIT(1);
    __syncthreads();

    uint32_t qa[4][2][4];
#pragma unroll
    for (int ks = 0; ks < 4; ks++)
#pragma unroll
        for (int mi = 0; mi < 2; mi++)
            ldsm_x4(qa[ks][mi], &Qs[(warp * 32 + mi * 16 + rA) * LDH + ks * 16 + cA]);

    float o[2][8][4];
#pragma unroll
    for (int mi = 0; mi < 2; mi++)
#pragma unroll
        for (int ni = 0; ni < 8; ni++)
#pragma unroll
            for (int r = 0; r < 4; r++) o[mi][ni][r] = 0.0f;
    float l[2][2] = {{0.0f, 0.0f}, {0.0f, 0.0f}};

    const int NT = NN / BKV;
    for (int it = 0; it < NT; it++) {
        if (it > 0) {
            if (it + 1 < NT) CP_WAIT(1); else CP_WAIT(0);
            __syncthreads();                // single barrier per tile
        }
        if (it + 2 < NT) { loadKV((it + 2) % 3, (it + 2) * BKV); CP_COMMIT(); }

        const int s = it % 3;

        // ---- S' = (Q*log2e/sqrt(D)) K^T ----
        float sc[2][8][4];
#pragma unroll
        for (int mi = 0; mi < 2; mi++)
#pragma unroll
            for (int ni = 0; ni < 8; ni++)
#pragma unroll
                for (int r = 0; r < 4; r++) sc[mi][ni][r] = 0.0f;

#pragma unroll
        for (int ks = 0; ks < 4; ks++) {
#pragma unroll
            for (int nip = 0; nip < 4; nip++) {
                uint32_t b[4];
                ldsm_x4(b, &Ks[(s * BKV + nip * 16 + rB) * LDH + ks * 16 + cB]);
#pragma unroll
                for (int mi = 0; mi < 2; mi++) {
                    mma_f16(sc[mi][2 * nip], qa[ks][mi], b[0], b[1]);
                    mma_f16(sc[mi][2 * nip + 1], qa[ks][mi], b[2], b[3]);
                }
            }
        }

        // ---- P = exp2(S') in fp16x2; l summed from the same P ----
        uint32_t ph[2][8][2];
#pragma unroll
        for (int mi = 0; mi < 2; mi++) {
            float ps0 = 0.0f, ps1 = 0.0f;
#pragma unroll
            for (int ni = 0; ni < 8; ni++) {
                __half2 h0 = __floats2half2_rn(sc[mi][ni][0], sc[mi][ni][1]);
                __half2 h1 = __floats2half2_rn(sc[mi][ni][2], sc[mi][ni][3]);
                uint32_t e0 = h2exp2_u32(*(uint32_t*)&h0);
                uint32_t e1 = h2exp2_u32(*(uint32_t*)&h1);
                ph[mi][ni][0] = e0;
                ph[mi][ni][1] = e1;
                float2 f0 = __half22float2(*(__half2*)&e0);
                float2 f1 = __half22float2(*(__half2*)&e1);
                ps0 += f0.x + f0.y;
                ps1 += f1.x + f1.y;
            }
            l[mi][0] += ps0;
            l[mi][1] += ps1;
        }

        // ---- O += P V (V row-major -> trans ldsm; b reused across mi) ----
#pragma unroll
        for (int ks = 0; ks < 4; ks++) {
#pragma unroll
            for (int nip = 0; nip < 4; nip++) {
                uint32_t b[4];
                ldsm_x4_t(b, &Vs[(s * BKV + ks * 16 + rB) * LDH + nip * 16 + cB]);
#pragma unroll
                for (int mi = 0; mi < 2; mi++) {
                    uint32_t pa[4] = { ph[mi][2 * ks][0], ph[mi][2 * ks][1],
                                       ph[mi][2 * ks + 1][0], ph[mi][2 * ks + 1][1] };
                    mma_f16(o[mi][2 * nip], pa, b[0], b[2]);
                    mma_f16(o[mi][2 * nip + 1], pa, b[1], b[3]);
                }
            }
        }
    }

#pragma unroll
    for (int mi = 0; mi < 2; mi++) {
        float l0 = l[mi][0], l1 = l[mi][1];
        l0 += __shfl_xor_sync(0xffffffffu, l0, 1);
        l0 += __shfl_xor_sync(0xffffffffu, l0, 2);
        l1 += __shfl_xor_sync(0xffffffffu, l1, 1);
        l1 += __shfl_xor_sync(0xffffffffu, l1, 2);
        float inv0 = 1.0f / l0, inv1 = 1.0f / l1;
        size_t base = (size_t)(q0 + warp * 32 + mi * 16 + g) * DD + h * HD;
#pragma unroll
        for (int ni = 0; ni < 8; ni++) {
            int col = ni * 8 + 2 * t;
            *(__half2*)&O[base + col] = __floats2half2_rn(o[mi][ni][0] * inv0, o[mi][ni][1] * inv0);
            *(__half2*)&O[base + 8 * DD + col] = __floats2half2_rn(o[mi][ni][2] * inv1, o[mi][ni][3] * inv1);
        }
    }
}

// ---------------------------------------------------------------------------
// kernel_launch: query,key,value, Wq,bq, Wk,bk, Wv,bv, Wo,bo, sgconv_mat
// ---------------------------------------------------------------------------
extern "C" void kernel_launch(void* const* d_in, const int* in_sizes, int n_in,
                              void* d_out, int out_size) {
    const float* query  = (const float*)d_in[0];
    const float* key    = (const float*)d_in[1];
    const float* value  = (const float*)d_in[2];
    const float* Wq     = (const float*)d_in[3];
    const float* bq     = (const float*)d_in[4];
    const float* Wk     = (const float*)d_in[5];
    const float* bk     = (const float*)d_in[6];
    const float* Wv     = (const float*)d_in[7];
    const float* bv     = (const float*)d_in[8];
    const float* Wo     = (const float*)d_in[9];
    const float* bo     = (const float*)d_in[10];
    const float* sgconv = (const float*)d_in[11];
    float* out = (float*)d_out;

    __half *xh, *wh, *qkv, *ah, *sgh, *gch, *parth;
    cudaGetSymbolAddress((void**)&xh, g_x);
    cudaGetSymbolAddress((void**)&wh, g_w);
    cudaGetSymbolAddress((void**)&qkv, g_qkv);
    cudaGetSymbolAddress((void**)&ah, g_ah);
    cudaGetSymbolAddress((void**)&sgh, g_sg_h);
    cudaGetSymbolAddress((void**)&gch, g_gc_h);
    cudaGetSymbolAddress((void**)&parth, g_parth);

    const int FLASH_SMEM = (BQ * LDH + 6 * BKV * LDH) * (int)sizeof(__half);
    cudaFuncSetAttribute(flash_attn, cudaFuncAttributeMaxDynamicSharedMemorySize, FLASH_SMEM);
    const int HG_SMEM_T128 = (3 * 128 * ALD + 3 * 128 * BLD_T) * (int)sizeof(__half);
    const int HG_SMEM_T64  = (3 * 128 * ALD + 3 * 64 * BLD_T) * (int)sizeof(__half);
    const int HG_SMEM_N    = (3 * 128 * ALD + 3 * 64 * BLD_N) * (int)sizeof(__half);
    cudaFuncSetAttribute(hgemm<128, true, true, 1>,   cudaFuncAttributeMaxDynamicSharedMemorySize, HG_SMEM_T128);
    cudaFuncSetAttribute(hgemm<64, true, true, 0>,    cudaFuncAttributeMaxDynamicSharedMemorySize, HG_SMEM_T64);
    cudaFuncSetAttribute(hgemm<128, false, false, 1>, cudaFuncAttributeMaxDynamicSharedMemorySize, HG_SMEM_N);

    // 1/sqrt(512) * log2(e): flash uses exp2
    const float qscale = 0.04419417382415922f * 1.4426950408889634f;

    // one convert launch for q,k,v + all four weights
    const int CVT_BLOCKS = (3 * NXD + 4 * NW) / 2048;   // 3584
    f2h_all<<<CVT_BLOCKS, 256>>>(query, key, value, Wq, Wk, Wv, Wo, xh, wh);

    // QKV projections, one batched launch: grid (4, 32, 3) = 384 CTAs
    dim3 gqkv(DD / 128, NN / 128, 3);
    hgemm<128, true, true, 1><<<gqkv, 128, HG_SMEM_T128>>>(
        xh, DD, NXD, wh, DD, NW, bq, bk, bv, qkv, DD, NXD, DD, qscale);

    // flash attention (256 CTAs) + concurrent sgconv convert (32 CTAs)
    dim3 agrid(NN / BQ, NH + 1);
    flash_attn<<<agrid, 128, FLASH_SMEM>>>(qkv, qkv + NXD, qkv + 2 * NXD, ah,
                                           sgconv, sgh);

    // graph conv split-K=2: grid (4, 32, 2) = 256 CTAs, fp16 partials
    dim3 gsg(DD / 128, NN / 128, 2);
    hgemm<128, false, false, 1><<<gsg, 128, HG_SMEM_N>>>(
        sgh, NN, 2048, ah, DD, (long)2048 * DD, nullptr, nullptr, nullptr,
        parth, DD, NXD, 2048, 1.0f);
    combine2h_kernel<<<NXD / 2048, 256>>>(parth, gch);

    // output projection: BN=64 -> grid (8, 32) = 256 CTAs (one full wave)
    dim3 gop(DD / 64, NN / 128, 1);
    hgemm<64, true, true, 0><<<gop, 128, HG_SMEM_T64>>>(
        gch, DD, 0, wh + 3 * (size_t)NW, DD, 0, bo, nullptr, nullptr,
        out, DD, 0, DD, 1.0f);
}